// round 2
// baseline (speedup 1.0000x reference)
#include <cuda_runtime.h>
#include <math.h>

#define NB      8
#define CDIM    192
#define C3      576
#define NHEADS  8
#define CH      24
#define HWN     16384
#define WIDTH   128
#define HEIGHT  128

// ---------------- scratch (static device globals; no allocation) ----------------
static __device__ float g_qkv[(size_t)NB * C3 * HWN];     // 302 MB
static __device__ float g_qf [(size_t)NB * CDIM * HWN];   // 100 MB
static __device__ float g_kf [(size_t)NB * CDIM * HWN];   // 100 MB
static __device__ float g_v  [(size_t)NB * CDIM * HWN];   // 100 MB
static __device__ float g_gram[NB * NHEADS * CH * CH];
static __device__ float g_nq[NB * CDIM];
static __device__ float g_nk[NB * CDIM];
static __device__ float g_M[NB * CDIM * CDIM];

// ---------------- f32x2 packed helpers ----------------
union U64F2 { unsigned long long u; float2 f; };

__device__ __forceinline__ unsigned long long pack2(float x) {
    unsigned long long r;
    asm("mov.b64 %0, {%1, %1};" : "=l"(r) : "f"(x));
    return r;
}
__device__ __forceinline__ void ffma2(unsigned long long& d,
                                      unsigned long long a,
                                      unsigned long long b) {
    asm("fma.rn.f32x2 %0, %1, %2, %0;" : "+l"(d) : "l"(a), "l"(b));
}

// ---------------- zero the atomic-accumulated buffers ----------------
__global__ void zero_kernel() {
    int i = blockIdx.x * 256 + threadIdx.x;
    if (i < NB * NHEADS * CH * CH) g_gram[i] = 0.f;
    if (i < NB * CDIM) { g_nq[i] = 0.f; g_nk[i] = 0.f; }
}

// ---------------- GEMM: Out[b, m, n] = sum_k A[b?, m, k] * X[b, k, n] ----------------
// K = 192 fixed. Tile: BM=96, BN=128, BK=32. 256 threads (8 warps).
// Warp = 12 M-rows x 128 N-cols; thread = 12 x 4 (as 12 x 2 f32x2 pairs).
__global__ void __launch_bounds__(256, 2)
gemm_f32(const float* __restrict__ A, long aStride,
         const float* __restrict__ X,
         float* __restrict__ Out, int Mdim)
{
    __shared__ float As[32][100];   // transposed A tile, pad for conflict-free
    __shared__ float Bs[32][128];

    const int tid = threadIdx.x;
    const int bn  = blockIdx.x;
    const int bm  = blockIdx.y;
    const int bb  = blockIdx.z;

    const float* Ab = A + (size_t)bb * aStride + (size_t)bm * 96 * CDIM;
    const float* Xb = X + (size_t)bb * CDIM * HWN + (size_t)bn * 128;
    float* Ob = Out + ((size_t)bb * Mdim + bm * 96) * HWN + (size_t)bn * 128;

    const int warp = tid >> 5;       // 0..7 -> M group of 12
    const int lane = tid & 31;       // N offset = lane*4

    const int ar = tid >> 3;         // base A row (chunks add +32)
    const int ac = (tid & 7) * 4;    // A col within 32
    const int br = tid >> 5;         // base B row (chunks add +8)
    const int bc = (tid & 31) * 4;   // B col within 128

    float4 aR[3], bR[4];
#pragma unroll
    for (int i = 0; i < 3; i++)
        aR[i] = *reinterpret_cast<const float4*>(Ab + (size_t)(ar + i * 32) * CDIM + ac);
#pragma unroll
    for (int i = 0; i < 4; i++)
        bR[i] = *reinterpret_cast<const float4*>(Xb + (size_t)(br + i * 8) * HWN + bc);

    unsigned long long acc[12][2];
#pragma unroll
    for (int i = 0; i < 12; i++) { acc[i][0] = 0ull; acc[i][1] = 0ull; }

#pragma unroll 1
    for (int kt = 0; kt < 6; kt++) {
        // stage regs -> smem (A transposed)
#pragma unroll
        for (int i = 0; i < 3; i++) {
            int r = ar + i * 32;
            As[ac + 0][r] = aR[i].x;
            As[ac + 1][r] = aR[i].y;
            As[ac + 2][r] = aR[i].z;
            As[ac + 3][r] = aR[i].w;
        }
#pragma unroll
        for (int i = 0; i < 4; i++)
            *reinterpret_cast<float4*>(&Bs[br + i * 8][bc]) = bR[i];
        __syncthreads();

        if (kt < 5) {
            const int k0 = (kt + 1) * 32;
#pragma unroll
            for (int i = 0; i < 3; i++)
                aR[i] = *reinterpret_cast<const float4*>(Ab + (size_t)(ar + i * 32) * CDIM + k0 + ac);
#pragma unroll
            for (int i = 0; i < 4; i++)
                bR[i] = *reinterpret_cast<const float4*>(Xb + (size_t)(k0 + br + i * 8) * HWN + bc);
        }

#pragma unroll
        for (int k = 0; k < 32; k++) {
            ulonglong2 bv = *reinterpret_cast<const ulonglong2*>(&Bs[k][lane * 4]);
            const float* ap = &As[k][warp * 12];
            float4 a0 = *reinterpret_cast<const float4*>(ap);
            float4 a1 = *reinterpret_cast<const float4*>(ap + 4);
            float4 a2 = *reinterpret_cast<const float4*>(ap + 8);
            float av[12] = {a0.x, a0.y, a0.z, a0.w,
                            a1.x, a1.y, a1.z, a1.w,
                            a2.x, a2.y, a2.z, a2.w};
#pragma unroll
            for (int i = 0; i < 12; i++) {
                unsigned long long p2 = pack2(av[i]);
                ffma2(acc[i][0], p2, bv.x);
                ffma2(acc[i][1], p2, bv.y);
            }
        }
        __syncthreads();
    }

#pragma unroll
    for (int i = 0; i < 12; i++) {
        U64F2 lo, hi;
        lo.u = acc[i][0];
        hi.u = acc[i][1];
        float4 o = make_float4(lo.f.x, lo.f.y, hi.f.x, hi.f.y);
        *reinterpret_cast<float4*>(Ob + (size_t)(warp * 12 + i) * HWN + lane * 4) = o;
    }
}

// ---------------- depthwise 3x3 conv + f-mult + qf/kf/v write + norm reduction ----
// grid: (16 rowblocks, 576 channels, 8 batch), block 128
__global__ void __launch_bounds__(128)
dwconv_kernel(const float* __restrict__ feat, const float* __restrict__ Wdw)
{
    __shared__ float t[10][130];
    __shared__ float wsum[4];
    const int x  = threadIdx.x;
    const int rb = blockIdx.x;
    const int c  = blockIdx.y;
    const int b  = blockIdx.z;

    const float* in = g_qkv + ((size_t)b * C3 + c) * HWN;
    const int r0 = rb * 8;

#pragma unroll
    for (int r = 0; r < 10; r++) {
        int gr = r0 + r - 1;
        t[r][x + 1] = (gr >= 0 && gr < HEIGHT) ? in[gr * WIDTH + x] : 0.f;
    }
    if (x < 10)       t[x][0] = 0.f;
    else if (x < 20)  t[x - 10][129] = 0.f;
    __syncthreads();

    float w[9];
#pragma unroll
    for (int i = 0; i < 9; i++) w[i] = Wdw[c * 9 + i];

    const int cl = (c < CDIM) ? c : (c < 2 * CDIM ? c - CDIM : c - 2 * CDIM);
    const float* fp = feat + ((size_t)b * CDIM + cl) * HWN;
    float* dst = (c < CDIM) ? (g_qf + ((size_t)b * CDIM + cl) * HWN)
               : (c < 2 * CDIM) ? (g_kf + ((size_t)b * CDIM + cl) * HWN)
                                : (g_v + ((size_t)b * CDIM + cl) * HWN);

    float sq = 0.f;
#pragma unroll
    for (int r = 0; r < 8; r++) {
        float s = t[r + 0][x + 0] * w[0] + t[r + 0][x + 1] * w[1] + t[r + 0][x + 2] * w[2]
                + t[r + 1][x + 0] * w[3] + t[r + 1][x + 1] * w[4] + t[r + 1][x + 2] * w[5]
                + t[r + 2][x + 0] * w[6] + t[r + 2][x + 1] * w[7] + t[r + 2][x + 2] * w[8];
        int p = (r0 + r) * WIDTH + x;
        if (c < 2 * CDIM) {
            float v = s * fp[p];
            dst[p] = v;
            sq += v * v;
        } else {
            dst[p] = s;
        }
    }

    if (c < 2 * CDIM) {
#pragma unroll
        for (int off = 16; off; off >>= 1)
            sq += __shfl_xor_sync(0xffffffffu, sq, off);
        if ((x & 31) == 0) wsum[x >> 5] = sq;
        __syncthreads();
        if (x == 0) {
            float tot = wsum[0] + wsum[1] + wsum[2] + wsum[3];
            atomicAdd(((c < CDIM) ? g_nq : g_nk) + b * CDIM + cl, tot);
        }
    }
}

// ---------------- Gram: G[b,h] = Qf Kf^T (24x24), reduced over 16384 ----------------
// grid: (16 slices, 8 heads, 8 batch), block 256.
// 16 subtiles of 6x6 (st = tid>>4), 16 position groups (pg = tid&15).
__global__ void __launch_bounds__(256)
gram_kernel()
{
    __shared__ float qs[24][132];
    __shared__ float ks[24][132];
    const int sl = blockIdx.x, h = blockIdx.y, b = blockIdx.z;
    const int tid = threadIdx.x;
    const int st = tid >> 4;
    const int pg = tid & 15;
    const int si = (st >> 2) * 6;
    const int sj = (st & 3) * 6;

    const float* Q = g_qf + ((size_t)b * CDIM + h * CH) * HWN + (size_t)sl * 1024;
    const float* K = g_kf + ((size_t)b * CDIM + h * CH) * HWN + (size_t)sl * 1024;

    float acc[6][6];
#pragma unroll
    for (int i = 0; i < 6; i++)
#pragma unroll
        for (int j = 0; j < 6; j++) acc[i][j] = 0.f;

    const int lr = tid >> 5;          // load row base (chunks add +8)
    const int lc = (tid & 31) * 4;    // load col

    for (int sub = 0; sub < 8; sub++) {
#pragma unroll
        for (int i = 0; i < 3; i++) {
            int r = lr + i * 8;
            *reinterpret_cast<float4*>(&qs[r][lc]) =
                *reinterpret_cast<const float4*>(Q + (size_t)r * HWN + sub * 128 + lc);
            *reinterpret_cast<float4*>(&ks[r][lc]) =
                *reinterpret_cast<const float4*>(K + (size_t)r * HWN + sub * 128 + lc);
        }
        __syncthreads();
#pragma unroll
        for (int pi = 0; pi < 8; pi++) {
            int p = pg + pi * 16;
            float qv[6], kv[6];
#pragma unroll
            for (int i = 0; i < 6; i++) { qv[i] = qs[si + i][p]; kv[i] = ks[sj + i][p]; }
#pragma unroll
            for (int i = 0; i < 6; i++)
#pragma unroll
                for (int j = 0; j < 6; j++) acc[i][j] += qv[i] * kv[j];
        }
        __syncthreads();
    }

    // reduce over 16 position groups (lanes [st*16, st*16+16) are contiguous)
#pragma unroll
    for (int i = 0; i < 6; i++)
#pragma unroll
        for (int j = 0; j < 6; j++) {
            float v = acc[i][j];
#pragma unroll
            for (int off = 8; off; off >>= 1)
                v += __shfl_xor_sync(0xffffffffu, v, off);
            if (pg == 0)
                atomicAdd(&g_gram[(((b * NHEADS + h) * CH) + si + i) * CH + sj + j], v);
        }
}

// ---------------- attn softmax + M[b] = Wp_block @ attn ----------------
// grid: 64 (b*heads), block 192
__global__ void __launch_bounds__(192)
buildM_kernel(const float* __restrict__ Wp, const float* __restrict__ temp)
{
    const int bh = blockIdx.x;
    const int b = bh >> 3, h = bh & 7;
    const int tid = threadIdx.x;

    __shared__ float sa[24][25];
    __shared__ float nqs[24], nks[24];

    if (tid < 24) {
        nqs[tid] = fmaxf(sqrtf(g_nq[b * CDIM + h * CH + tid]), 1e-12f);
        nks[tid] = fmaxf(sqrtf(g_nk[b * CDIM + h * CH + tid]), 1e-12f);
    }
    __syncthreads();

    const float tp = temp[h];
    for (int e = tid; e < CH * CH; e += 192) {
        int i = e / CH, j = e % CH;
        sa[i][j] = tp * g_gram[(bh * CH + i) * CH + j] / (nqs[i] * nks[j]);
    }
    __syncthreads();

    if (tid < 24) {
        float mx = sa[tid][0];
#pragma unroll
        for (int j = 1; j < 24; j++) mx = fmaxf(mx, sa[tid][j]);
        float s = 0.f;
#pragma unroll
        for (int j = 0; j < 24; j++) { float e = expf(sa[tid][j] - mx); sa[tid][j] = e; s += e; }
        float inv = 1.f / s;
#pragma unroll
        for (int j = 0; j < 24; j++) sa[tid][j] *= inv;
    }
    __syncthreads();

    // thread tid = output row o: M[b][o][h*24+j] = sum_i Wp[o][h*24+i] * attn[i][j]
    float wr[24];
#pragma unroll
    for (int i = 0; i < 24; i++) wr[i] = Wp[tid * CDIM + h * CH + i];
#pragma unroll
    for (int j = 0; j < 24; j++) {
        float s = 0.f;
#pragma unroll
        for (int i = 0; i < 24; i++) s += wr[i] * sa[i][j];
        g_M[((size_t)b * CDIM + tid) * CDIM + h * CH + j] = s;
    }
}

// ---------------- launch ----------------
extern "C" void kernel_launch(void* const* d_in, const int* in_sizes, int n_in,
                              void* d_out, int out_size)
{
    (void)in_sizes; (void)n_in; (void)out_size;
    const float* x     = (const float*)d_in[0];
    const float* feat  = (const float*)d_in[1];
    const float* Wqkv  = (const float*)d_in[2];
    const float* Wdw   = (const float*)d_in[3];
    const float* Wproj = (const float*)d_in[4];
    const float* temp  = (const float*)d_in[5];
    float* out = (float*)d_out;

    float *qkvP, *vP, *MP;
    cudaGetSymbolAddress((void**)&qkvP, g_qkv);
    cudaGetSymbolAddress((void**)&vP,   g_v);
    cudaGetSymbolAddress((void**)&MP,   g_M);

    zero_kernel<<<144, 256>>>();
    // qkv = W_qkv @ x  (576x192 @ 192x16384 per batch)
    gemm_f32<<<dim3(128, 6, NB), 256>>>(Wqkv, 0, x, qkvP, C3);
    // depthwise conv + f-mult + norms + qf/kf/v
    dwconv_kernel<<<dim3(16, C3, NB), 128>>>(feat, Wdw);
    // Gram matrices
    gram_kernel<<<dim3(16, NHEADS, NB), 256>>>();
    // softmax + fold proj into per-batch M
    buildM_kernel<<<NB * NHEADS, 192>>>(Wproj, temp);
    // final = M[b] @ v[b]  (192x192 @ 192x16384 per batch)
    gemm_f32<<<dim3(128, 2, NB), 256>>>(MP, (long)CDIM * CDIM, vP, out, CDIM);
}

// round 4
// speedup vs baseline: 1.5045x; 1.5045x over previous
#include <cuda_runtime.h>
#include <cuda_bf16.h>
#include <math.h>
#include <stdint.h>

#define NB      8
#define CDIM    192
#define C3      576
#define NHEADS  8
#define CH      24
#define HWN     16384
#define WIDTH   128
#define HEIGHT  128

// ---------------- scratch (static device globals; no allocation) ----------------
static __device__ float g_qkv[(size_t)NB * C3 * HWN];     // 302 MB
static __device__ float g_qf [(size_t)NB * CDIM * HWN];   // 100 MB
static __device__ float g_kf [(size_t)NB * CDIM * HWN];   // 100 MB
static __device__ float g_v  [(size_t)NB * CDIM * HWN];   // 100 MB
static __device__ float g_gram[NB * NHEADS * CH * CH];
static __device__ float g_nq[NB * CDIM];
static __device__ float g_nk[NB * CDIM];
static __device__ float g_M[NB * CDIM * CDIM];

// ---------------- helpers ----------------
__device__ __forceinline__ uint32_t smem_u32(const void* p) {
    uint32_t a;
    asm("{ .reg .u64 t; cvta.to.shared.u64 t, %1; cvt.u32.u64 %0, t; }"
        : "=r"(a) : "l"(p));
    return a;
}
__device__ __forceinline__ uint32_t pack_bf2(float a, float b) {
    __nv_bfloat162 t = __floats2bfloat162_rn(a, b);
    return *reinterpret_cast<uint32_t*>(&t);
}
__device__ __forceinline__ void ldsm_x4(uint32_t* r, uint32_t addr) {
    asm volatile("ldmatrix.sync.aligned.m8n8.x4.shared.b16 {%0,%1,%2,%3}, [%4];"
                 : "=r"(r[0]), "=r"(r[1]), "=r"(r[2]), "=r"(r[3]) : "r"(addr));
}
__device__ __forceinline__ void ldsm_x2t(uint32_t* r, uint32_t addr) {
    asm volatile("ldmatrix.sync.aligned.m8n8.x2.trans.shared.b16 {%0,%1}, [%2];"
                 : "=r"(r[0]), "=r"(r[1]) : "r"(addr));
}
__device__ __forceinline__ void mma16816(float* c, const uint32_t* a, const uint32_t* b) {
    asm volatile(
        "mma.sync.aligned.m16n8k16.row.col.f32.bf16.bf16.f32 "
        "{%0,%1,%2,%3}, {%4,%5,%6,%7}, {%8,%9}, {%0,%1,%2,%3};"
        : "+f"(c[0]), "+f"(c[1]), "+f"(c[2]), "+f"(c[3])
        : "r"(a[0]), "r"(a[1]), "r"(a[2]), "r"(a[3]), "r"(b[0]), "r"(b[1]));
}

// ---------------- zero the atomic-accumulated buffers ----------------
__global__ void zero_kernel() {
    int i = blockIdx.x * 256 + threadIdx.x;
    if (i < NB * NHEADS * CH * CH) g_gram[i] = 0.f;
    if (i < NB * CDIM) { g_nq[i] = 0.f; g_nk[i] = 0.f; }
}

// ---------------- bf16 split-precision mma.sync GEMM ----------------
// Out[b, m0..m0+127, n0..n0+127] = A[b?, 128x192] @ X[b, 192, n0..n0+127]
// 3-pass split: hi*hi + lo*hi + hi*lo, fp32 accumulate.
#define SA_STR 40    // A smem row stride (bf16): 80B, conflict-free for ldmatrix
#define SB_STR 136   // B smem row stride (bf16): 272B, conflict-free for ldmatrix

__global__ void __launch_bounds__(256, 2)
gemm_mma(const float* __restrict__ A, long aBatch,
         const float* __restrict__ X,
         float* __restrict__ Out, int Mrows)
{
    __shared__ __nv_bfloat16 sAhi[128 * SA_STR];
    __shared__ __nv_bfloat16 sAlo[128 * SA_STR];
    __shared__ __nv_bfloat16 sBhi[32 * SB_STR];
    __shared__ __nv_bfloat16 sBlo[32 * SB_STR];

    const int tid  = threadIdx.x;
    const int wid  = tid >> 5;
    const int lane = tid & 31;
    const int wm   = wid & 1;   // 2 warp rows of 64
    const int wn   = wid >> 1;  // 4 warp cols of 32

    const int m0 = min((int)blockIdx.x * 128, Mrows - 128);
    const int n0 = blockIdx.y * 128;
    const int bb = blockIdx.z;

    const float* Ab = A + (size_t)bb * (size_t)aBatch + (size_t)m0 * CDIM;
    const float* Xb = X + (size_t)bb * CDIM * (size_t)HWN + n0;
    float* Ob = Out + ((size_t)bb * Mrows + m0) * (size_t)HWN + n0;

    const uint32_t sAhiB = smem_u32(sAhi);
    const uint32_t sAloB = smem_u32(sAlo);
    const uint32_t sBhiB = smem_u32(sBhi);
    const uint32_t sBloB = smem_u32(sBlo);

    float acc[4][4][4];
#pragma unroll
    for (int mt = 0; mt < 4; mt++)
#pragma unroll
        for (int nt = 0; nt < 4; nt++)
#pragma unroll
            for (int e = 0; e < 4; e++) acc[mt][nt][e] = 0.f;

#pragma unroll 1
    for (int kt = 0; kt < 6; kt++) {
        // ---- stage A: 128 rows x 32 k ----
#pragma unroll
        for (int i = 0; i < 4; i++) {
            int id = tid + i * 256;
            int r = id >> 3, k4 = (id & 7) << 2;
            float4 v = *reinterpret_cast<const float4*>(Ab + (size_t)r * CDIM + kt * 32 + k4);
            float h0 = __bfloat162float(__float2bfloat16_rn(v.x));
            float h1 = __bfloat162float(__float2bfloat16_rn(v.y));
            float h2 = __bfloat162float(__float2bfloat16_rn(v.z));
            float h3 = __bfloat162float(__float2bfloat16_rn(v.w));
            uint2 hi = make_uint2(pack_bf2(v.x, v.y), pack_bf2(v.z, v.w));
            uint2 lo = make_uint2(pack_bf2(v.x - h0, v.y - h1), pack_bf2(v.z - h2, v.w - h3));
            *reinterpret_cast<uint2*>(&sAhi[r * SA_STR + k4]) = hi;
            *reinterpret_cast<uint2*>(&sAlo[r * SA_STR + k4]) = lo;
        }
        // ---- stage B: 32 k x 128 n ----
#pragma unroll
        for (int i = 0; i < 4; i++) {
            int id = tid + i * 256;
            int kr = id >> 5, n4 = (id & 31) << 2;
            float4 v = *reinterpret_cast<const float4*>(Xb + (size_t)(kt * 32 + kr) * HWN + n4);
            float h0 = __bfloat162float(__float2bfloat16_rn(v.x));
            float h1 = __bfloat162float(__float2bfloat16_rn(v.y));
            float h2 = __bfloat162float(__float2bfloat16_rn(v.z));
            float h3 = __bfloat162float(__float2bfloat16_rn(v.w));
            uint2 hi = make_uint2(pack_bf2(v.x, v.y), pack_bf2(v.z, v.w));
            uint2 lo = make_uint2(pack_bf2(v.x - h0, v.y - h1), pack_bf2(v.z - h2, v.w - h3));
            *reinterpret_cast<uint2*>(&sBhi[kr * SB_STR + n4]) = hi;
            *reinterpret_cast<uint2*>(&sBlo[kr * SB_STR + n4]) = lo;
        }
        __syncthreads();

#pragma unroll
        for (int k16 = 0; k16 < 2; k16++) {
            // B fragments: 4 n-tiles, hi & lo
            uint32_t bh[4][2], bl[4][2];
            {
                int krow = k16 * 16 + (lane & 15);
                int ncol = wn * 32;
#pragma unroll
                for (int nt = 0; nt < 4; nt++) {
                    uint32_t off = (uint32_t)(krow * SB_STR + ncol + nt * 8) * 2;
                    ldsm_x2t(bh[nt], sBhiB + off);
                    ldsm_x2t(bl[nt], sBloB + off);
                }
            }
#pragma unroll
            for (int mt = 0; mt < 4; mt++) {
                uint32_t ah[4], al[4];
                int arow = wm * 64 + mt * 16 + (lane & 15);
                int acol = k16 * 16 + (lane >> 4) * 8;
                uint32_t off = (uint32_t)(arow * SA_STR + acol) * 2;
                ldsm_x4(ah, sAhiB + off);
                ldsm_x4(al, sAloB + off);
#pragma unroll
                for (int nt = 0; nt < 4; nt++) {
                    mma16816(acc[mt][nt], ah, bh[nt]);
                    mma16816(acc[mt][nt], al, bh[nt]);
                    mma16816(acc[mt][nt], ah, bl[nt]);
                }
            }
        }
        __syncthreads();
    }

    // ---- epilogue ----
    const int rin = lane >> 2;
    const int cin = (lane & 3) * 2;
#pragma unroll
    for (int mt = 0; mt < 4; mt++) {
#pragma unroll
        for (int nt = 0; nt < 4; nt++) {
            int m = wm * 64 + mt * 16 + rin;
            int n = wn * 32 + nt * 8 + cin;
            *reinterpret_cast<float2*>(Ob + (size_t)m * HWN + n) =
                make_float2(acc[mt][nt][0], acc[mt][nt][1]);
            *reinterpret_cast<float2*>(Ob + (size_t)(m + 8) * HWN + n) =
                make_float2(acc[mt][nt][2], acc[mt][nt][3]);
        }
    }
}

// ---------------- fused depthwise 3x3 conv for q,k,v triple + norms ----------------
// grid: (16 rowblocks, 192 channels, 8 batch), block 128
__global__ void __launch_bounds__(128)
dwconv3_kernel(const float* __restrict__ feat, const float* __restrict__ Wdw)
{
    __shared__ float t[3][10][130];
    __shared__ float wsq[4], wsk[4];
    const int x  = threadIdx.x;
    const int rb = blockIdx.x;
    const int cl = blockIdx.y;
    const int b  = blockIdx.z;

    const int r0 = rb * 8;
#pragma unroll
    for (int ch = 0; ch < 3; ch++) {
        const float* in = g_qkv + ((size_t)b * C3 + cl + ch * CDIM) * HWN;
#pragma unroll
        for (int r = 0; r < 10; r++) {
            int gr = r0 + r - 1;
            t[ch][r][x + 1] = (gr >= 0 && gr < HEIGHT) ? in[gr * WIDTH + x] : 0.f;
        }
        if (x < 10)       t[ch][x][0] = 0.f;
        else if (x < 20)  t[ch][x - 10][129] = 0.f;
    }
    __syncthreads();

    float wq[9], wk[9], wv[9];
#pragma unroll
    for (int i = 0; i < 9; i++) {
        wq[i] = Wdw[(cl) * 9 + i];
        wk[i] = Wdw[(cl + CDIM) * 9 + i];
        wv[i] = Wdw[(cl + 2 * CDIM) * 9 + i];
    }

    const float* fp = feat + ((size_t)b * CDIM + cl) * HWN;
    float* dq = g_qf + ((size_t)b * CDIM + cl) * HWN;
    float* dk = g_kf + ((size_t)b * CDIM + cl) * HWN;
    float* dv = g_v  + ((size_t)b * CDIM + cl) * HWN;

    float sumq = 0.f, sumk = 0.f;
#pragma unroll
    for (int r = 0; r < 8; r++) {
        float sq = 0.f, sk = 0.f, sv = 0.f;
#pragma unroll
        for (int dy = 0; dy < 3; dy++)
#pragma unroll
            for (int dx = 0; dx < 3; dx++) {
                float tq = t[0][r + dy][x + dx];
                float tk = t[1][r + dy][x + dx];
                float tv = t[2][r + dy][x + dx];
                int wi = dy * 3 + dx;
                sq += tq * wq[wi];
                sk += tk * wk[wi];
                sv += tv * wv[wi];
            }
        int p = (r0 + r) * WIDTH + x;
        float f = fp[p];
        float qv = sq * f, kv = sk * f;
        dq[p] = qv; dk[p] = kv; dv[p] = sv;
        sumq += qv * qv; sumk += kv * kv;
    }

#pragma unroll
    for (int off = 16; off; off >>= 1) {
        sumq += __shfl_xor_sync(0xffffffffu, sumq, off);
        sumk += __shfl_xor_sync(0xffffffffu, sumk, off);
    }
    if ((x & 31) == 0) { wsq[x >> 5] = sumq; wsk[x >> 5] = sumk; }
    __syncthreads();
    if (x == 0) {
        atomicAdd(g_nq + b * CDIM + cl, wsq[0] + wsq[1] + wsq[2] + wsq[3]);
        atomicAdd(g_nk + b * CDIM + cl, wsk[0] + wsk[1] + wsk[2] + wsk[3]);
    }
}

// ---------------- Gram: G[b,h] = Qf Kf^T (24x24) ----------------
__global__ void __launch_bounds__(256)
gram_kernel()
{
    __shared__ float qs[24][132];
    __shared__ float ks[24][132];
    const int sl = blockIdx.x, h = blockIdx.y, b = blockIdx.z;
    const int tid = threadIdx.x;
    const int st = tid >> 4;
    const int pg = tid & 15;
    const int si = (st >> 2) * 6;
    const int sj = (st & 3) * 6;

    const float* Q = g_qf + ((size_t)b * CDIM + h * CH) * HWN + (size_t)sl * 1024;
    const float* K = g_kf + ((size_t)b * CDIM + h * CH) * HWN + (size_t)sl * 1024;

    float acc[6][6];
#pragma unroll
    for (int i = 0; i < 6; i++)
#pragma unroll
        for (int j = 0; j < 6; j++) acc[i][j] = 0.f;

    const int lr = tid >> 5;
    const int lc = (tid & 31) * 4;

    for (int sub = 0; sub < 8; sub++) {
#pragma unroll
        for (int i = 0; i < 3; i++) {
            int r = lr + i * 8;
            *reinterpret_cast<float4*>(&qs[r][lc]) =
                *reinterpret_cast<const float4*>(Q + (size_t)r * HWN + sub * 128 + lc);
            *reinterpret_cast<float4*>(&ks[r][lc]) =
                *reinterpret_cast<const float4*>(K + (size_t)r * HWN + sub * 128 + lc);
        }
        __syncthreads();
#pragma unroll
        for (int pi = 0; pi < 8; pi++) {
            int p = pg + pi * 16;
            float qv[6], kv[6];
#pragma unroll
            for (int i = 0; i < 6; i++) { qv[i] = qs[si + i][p]; kv[i] = ks[sj + i][p]; }
#pragma unroll
            for (int i = 0; i < 6; i++)
#pragma unroll
                for (int j = 0; j < 6; j++) acc[i][j] += qv[i] * kv[j];
        }
        __syncthreads();
    }

#pragma unroll
    for (int i = 0; i < 6; i++)
#pragma unroll
        for (int j = 0; j < 6; j++) {
            float v = acc[i][j];
#pragma unroll
            for (int off = 8; off; off >>= 1)
                v += __shfl_xor_sync(0xffffffffu, v, off);
            if (pg == 0)
                atomicAdd(&g_gram[(((b * NHEADS + h) * CH) + si + i) * CH + sj + j], v);
        }
}

// ---------------- attn softmax + M[b] = Wp_block @ attn ----------------
__global__ void __launch_bounds__(192)
buildM_kernel(const float* __restrict__ Wp, const float* __restrict__ temp)
{
    const int bh = blockIdx.x;
    const int b = bh >> 3, h = bh & 7;
    const int tid = threadIdx.x;

    __shared__ float sa[24][25];
    __shared__ float nqs[24], nks[24];

    if (tid < 24) {
        nqs[tid] = fmaxf(sqrtf(g_nq[b * CDIM + h * CH + tid]), 1e-12f);
        nks[tid] = fmaxf(sqrtf(g_nk[b * CDIM + h * CH + tid]), 1e-12f);
    }
    __syncthreads();

    const float tp = temp[h];
    for (int e = tid; e < CH * CH; e += 192) {
        int i = e / CH, j = e % CH;
        sa[i][j] = tp * g_gram[(bh * CH + i) * CH + j] / (nqs[i] * nks[j]);
    }
    __syncthreads();

    if (tid < 24) {
        float mx = sa[tid][0];
#pragma unroll
        for (int j = 1; j < 24; j++) mx = fmaxf(mx, sa[tid][j]);
        float s = 0.f;
#pragma unroll
        for (int j = 0; j < 24; j++) { float e = expf(sa[tid][j] - mx); sa[tid][j] = e; s += e; }
        float inv = 1.f / s;
#pragma unroll
        for (int j = 0; j < 24; j++) sa[tid][j] *= inv;
    }
    __syncthreads();

    float wr[24];
#pragma unroll
    for (int i = 0; i < 24; i++) wr[i] = Wp[tid * CDIM + h * CH + i];
#pragma unroll
    for (int j = 0; j < 24; j++) {
        float s = 0.f;
#pragma unroll
        for (int i = 0; i < 24; i++) s += wr[i] * sa[i][j];
        g_M[((size_t)b * CDIM + tid) * CDIM + h * CH + j] = s;
    }
}

// ---------------- launch ----------------
extern "C" void kernel_launch(void* const* d_in, const int* in_sizes, int n_in,
                              void* d_out, int out_size)
{
    (void)in_sizes; (void)n_in; (void)out_size;
    const float* x     = (const float*)d_in[0];
    const float* feat  = (const float*)d_in[1];
    const float* Wqkv  = (const float*)d_in[2];
    const float* Wdw   = (const float*)d_in[3];
    const float* Wproj = (const float*)d_in[4];
    const float* temp  = (const float*)d_in[5];
    float* out = (float*)d_out;

    float *qkvP, *vP, *MP;
    cudaGetSymbolAddress((void**)&qkvP, g_qkv);
    cudaGetSymbolAddress((void**)&vP,   g_v);
    cudaGetSymbolAddress((void**)&MP,   g_M);

    zero_kernel<<<144, 256>>>();
    // qkv = W_qkv @ x : 576x16384 per batch, 5 overlapping M-tiles of 128
    gemm_mma<<<dim3(5, 128, NB), 256>>>(Wqkv, 0, x, qkvP, C3);
    // fused depthwise conv (q,k,v) + f-mult + norms
    dwconv3_kernel<<<dim3(16, CDIM, NB), 128>>>(feat, Wdw);
    // Gram matrices
    gram_kernel<<<dim3(16, NHEADS, NB), 256>>>();
    // softmax + fold proj into per-batch M
    buildM_kernel<<<NB * NHEADS, 192>>>(Wproj, temp);
    // final = M[b] @ v[b] : 192x16384 per batch, 2 overlapping M-tiles of 128
    gemm_mma<<<dim3(2, 128, NB), 256>>>(MP, (long)CDIM * CDIM, vP, out, CDIM);
}